// round 7
// baseline (speedup 1.0000x reference)
#include <cuda_runtime.h>
#include <cuda_fp16.h>
#include <math.h>

#define N_NODES 100000
#define N_EDGES 20000
#define NNZ     1600000
#define D       128
#define NB_V    ((N_NODES + 1023) / 1024)   // 98
#define NB_E    ((N_EDGES + 1023) / 1024)   // 20

// ---------------- scratch (device globals: allocation-free rule) ----------------
// Invariant: g_cnt_v/g_cnt_e/g_state_v/g_state_e are ZERO at entry (statically
// zero-initialized; re-zeroed by fill_edge_kernel after last use each execution).
__device__ int   g_cnt_v[N_NODES];
__device__ int   g_cnt_e[N_EDGES];
__device__ unsigned long long g_state_v[NB_V];    // lookback: (value<<2)|flag
__device__ unsigned long long g_state_e[NB_E];
__device__ int   g_offs_v[N_NODES + 1];
__device__ int   g_offs_e[N_EDGES + 1];
__device__ int   g_pos[NNZ];                      // (pos_v << 16) | pos_e
__device__ float g_inv_sqrt_dv[N_NODES];
__device__ float g_inv_de[N_EDGES];
__device__ int   g_edge_adj[NNZ];                 // per-edge list of vertex ids
__device__ int   g_node_adj[NNZ];                 // per-node list of edge ids
__device__ unsigned g_Xh[(size_t)N_NODES * 64];   // X in half2 bit patterns
__device__ float g_Yp[(size_t)N_EDGES * D];       // inv_de * H^T Dv^-1/2 X (fp32)
__device__ float g_se[N_EDGES];                   // inv_de * H^T Dv^-1/2 1
__device__ unsigned g_Yeh[(size_t)N_EDGES * 64];  // Ye in half2

// ---------------- A (aux stream): X -> half2 convert ----------------
__global__ void convert_kernel(const float* __restrict__ X) {
    int i = blockIdx.x * blockDim.x + threadIdx.x;
    if (i < N_NODES * 32) {
        float4 p = ((const float4*)X)[i];
        __half2 a = __floats2half2_rn(p.x, p.y);
        __half2 b = __floats2half2_rn(p.z, p.w);
        uint2 r;
        r.x = *reinterpret_cast<const unsigned*>(&a);
        r.y = *reinterpret_cast<const unsigned*>(&b);
        ((uint2*)g_Xh)[i] = r;
    }
}

// ---------------- 1: degree histograms + packed rank capture ----------------
__global__ void degree_kernel(const int* __restrict__ v_idx, const int* __restrict__ e_idx) {
    int i = blockIdx.x * blockDim.x + threadIdx.x;
    if (i < NNZ) {
        int pv = atomicAdd(&g_cnt_v[v_idx[i]], 1);
        int pe = atomicAdd(&g_cnt_e[e_idx[i]], 1);
        g_pos[i] = (pv << 16) | pe;
    }
}

// ---------------- 2: single-pass decoupled-lookback scan (both arrays) + inv factors ----------------
__global__ void scan_fused_kernel() {
    __shared__ int wsum[32];
    __shared__ int s_agg;
    __shared__ int s_prefix;
    int tid = threadIdx.x;                        // 1024
    int b = blockIdx.x;
    int chain_e = (b >= NB_V);
    int pb = chain_e ? (b - NB_V) : b;
    const int* in   = chain_e ? g_cnt_e : g_cnt_v;
    int*       out  = chain_e ? g_offs_e : g_offs_v;
    int        n    = chain_e ? N_EDGES : N_NODES;
    unsigned long long* st = chain_e ? g_state_e : g_state_v;

    int i = pb * 1024 + tid;
    int x = (i < n) ? in[i] : 0;

    if (i < n) {
        if (chain_e) g_inv_de[i] = (x > 0) ? (1.0f / (float)x) : 0.0f;
        else         g_inv_sqrt_dv[i] = (x > 0) ? rsqrtf((float)x) : 0.0f;
    }

    int v = x;
    #pragma unroll
    for (int o = 1; o < 32; o <<= 1) {
        int t = __shfl_up_sync(0xFFFFFFFFu, v, o);
        if ((tid & 31) >= o) v += t;
    }
    if ((tid & 31) == 31) wsum[tid >> 5] = v;
    __syncthreads();
    if (tid < 32) {
        int w = wsum[tid];
        #pragma unroll
        for (int o = 1; o < 32; o <<= 1) {
            int t = __shfl_up_sync(0xFFFFFFFFu, w, o);
            if (tid >= o) w += t;
        }
        wsum[tid] = w;
    }
    __syncthreads();
    int warppre = (tid >= 32) ? wsum[(tid >> 5) - 1] : 0;
    int incl = v + warppre;
    if (tid == 1023) s_agg = incl;
    __syncthreads();

    if (tid < 32) {
        int agg = s_agg;
        int run = 0;
        if (pb == 0) {
            if (tid == 0) atomicExch(&st[0], ((unsigned long long)agg << 2) | 2ULL);
        } else {
            if (tid == 0) atomicExch(&st[pb], ((unsigned long long)agg << 2) | 1ULL);
            __syncwarp();
            int p = pb - 1;
            while (true) {
                int idx = p - (int)tid;
                int flag;
                int val = 0;
                if (idx >= 0) {
                    unsigned long long s;
                    do { s = atomicAdd(&st[idx], 0ULL); flag = (int)(s & 3ULL); } while (flag == 0);
                    val = (int)(s >> 2);
                } else {
                    flag = 2;
                }
                unsigned m2 = __ballot_sync(0xFFFFFFFFu, flag == 2);
                int k = __ffs(m2) - 1;
                int contrib = (m2 == 0u || (int)tid <= k) ? val : 0;
                #pragma unroll
                for (int o = 16; o; o >>= 1) contrib += __shfl_down_sync(0xFFFFFFFFu, contrib, o);
                contrib = __shfl_sync(0xFFFFFFFFu, contrib, 0);
                run += contrib;
                if (m2) break;
                p -= 32;
            }
            if (tid == 0) atomicExch(&st[pb], ((unsigned long long)(agg + run) << 2) | 2ULL);
        }
        if (tid == 0) s_prefix = run;
    }
    __syncthreads();

    if (i < n) out[i] = s_prefix + incl - x;
    if (b == 0 && tid == 0) {
        g_offs_v[N_NODES] = NNZ;
        g_offs_e[N_EDGES] = NNZ;
    }
}

// ---------------- 3a: edge-side CSR fill + re-zero counters/states ----------------
__global__ void fill_edge_kernel(const int* __restrict__ v_idx, const int* __restrict__ e_idx) {
    int i = blockIdx.x * blockDim.x + threadIdx.x;
    if (i < NNZ) {
        int v = v_idx[i];
        int e = e_idx[i];
        int p = g_pos[i];
        g_edge_adj[g_offs_e[e] + (p & 0xFFFF)] = v;
    }
    // last use of counters/states was scan_fused_kernel -> safe to re-zero here
    if (i < N_NODES) g_cnt_v[i] = 0;
    if (i < N_EDGES) g_cnt_e[i] = 0;
    if (i < NB_V) g_state_v[i] = 0ULL;
    if (i < NB_E) g_state_e[i] = 0ULL;
}

// ---------------- 3b (aux stream): node-side CSR fill ----------------
__global__ void fill_node_kernel(const int* __restrict__ v_idx, const int* __restrict__ e_idx) {
    int i = blockIdx.x * blockDim.x + threadIdx.x;
    if (i < NNZ) {
        int v = v_idx[i];
        int e = e_idx[i];
        int p = g_pos[i];
        g_node_adj[g_offs_v[v] + (p >> 16)] = e;
    }
}

// ---------------- 4: edge gather-reduce (half2 X, 8-unrolled) ----------------
__global__ void edge_reduce_kernel() {
    int gw = (blockIdx.x * blockDim.x + threadIdx.x) >> 5;
    if (gw >= N_EDGES) return;
    int lane = threadIdx.x & 31;
    int beg = g_offs_e[gw], end = g_offs_e[gw + 1];
    const uint2* Xh2 = (const uint2*)g_Xh;
    float sx = 0.f, sy = 0.f, sz = 0.f, sw = 0.f, ssum = 0.f;
    int j = beg;
    for (; j + 8 <= end; j += 8) {
        int vv[8]; float sc[8]; uint2 q[8];
        #pragma unroll
        for (int u = 0; u < 8; u++) vv[u] = g_edge_adj[j + u];
        #pragma unroll
        for (int u = 0; u < 8; u++) sc[u] = g_inv_sqrt_dv[vv[u]];
        #pragma unroll
        for (int u = 0; u < 8; u++) q[u] = Xh2[(size_t)vv[u] * 32 + lane];
        #pragma unroll
        for (int u = 0; u < 8; u++) {
            float2 a = __half22float2(*reinterpret_cast<__half2*>(&q[u].x));
            float2 b = __half22float2(*reinterpret_cast<__half2*>(&q[u].y));
            sx = fmaf(sc[u], a.x, sx);
            sy = fmaf(sc[u], a.y, sy);
            sz = fmaf(sc[u], b.x, sz);
            sw = fmaf(sc[u], b.y, sw);
            ssum += sc[u];
        }
    }
    for (; j < end; j++) {
        int v = g_edge_adj[j];
        float s = g_inv_sqrt_dv[v];
        uint2 q = Xh2[(size_t)v * 32 + lane];
        float2 a = __half22float2(*reinterpret_cast<__half2*>(&q.x));
        float2 b = __half22float2(*reinterpret_cast<__half2*>(&q.y));
        sx = fmaf(s, a.x, sx);
        sy = fmaf(s, a.y, sy);
        sz = fmaf(s, b.x, sz);
        sw = fmaf(s, b.y, sw);
        ssum += s;
    }
    float s = g_inv_de[gw];
    ((float4*)g_Yp)[(size_t)gw * 32 + lane] = make_float4(sx * s, sy * s, sz * s, sw * s);
    if (lane == 0) g_se[gw] = ssum * s;
}

// ---------------- 5: small GEMM  Ye = Yp @ W + se * b  (fp32 math, half2 out) ----------------
#define BM 64
#define XS_STRIDE 132
#define GEMM_SMEM_BYTES ((128 * 128 + BM * XS_STRIDE + 128) * 4)

__global__ void __launch_bounds__(256)
gemm_edges_kernel(const float* __restrict__ W, const float* __restrict__ bias) {
    extern __shared__ float sm[];
    float* Wsm = sm;
    float* Ysm = sm + 128 * 128;
    float* bsm = Ysm + BM * XS_STRIDE;

    int tid = threadIdx.x;
    int row0 = blockIdx.x * BM;

    for (int i = tid; i < 128 * 32; i += 256)
        ((float4*)Wsm)[i] = ((const float4*)W)[i];
    if (tid < 32)
        ((float4*)bsm)[tid] = ((const float4*)bias)[tid];
    for (int i = tid; i < BM * 32; i += 256) {
        int m = i >> 5, kq = i & 31;
        int gr = row0 + m;
        float4 vv = (gr < N_EDGES) ? ((const float4*)(g_Yp + (size_t)gr * D))[kq]
                                   : make_float4(0.f, 0.f, 0.f, 0.f);
        *((float4*)(Ysm + m * XS_STRIDE + kq * 4)) = vv;
    }
    __syncthreads();

    int tx = tid & 31;
    int ty = tid >> 5;
    int c0 = tx * 4, r0 = ty * 8;

    float acc[8][4];
    #pragma unroll
    for (int j = 0; j < 8; j++) {
        acc[j][0] = 0.f; acc[j][1] = 0.f; acc[j][2] = 0.f; acc[j][3] = 0.f;
    }

    #pragma unroll 8
    for (int k = 0; k < 128; k++) {
        float4 b4 = *(const float4*)(Wsm + k * 128 + c0);
        #pragma unroll
        for (int j = 0; j < 8; j++) {
            float a = Ysm[(r0 + j) * XS_STRIDE + k];
            acc[j][0] = fmaf(a, b4.x, acc[j][0]);
            acc[j][1] = fmaf(a, b4.y, acc[j][1]);
            acc[j][2] = fmaf(a, b4.z, acc[j][2]);
            acc[j][3] = fmaf(a, b4.w, acc[j][3]);
        }
    }

    float4 bb = *(const float4*)(bsm + c0);
    #pragma unroll
    for (int j = 0; j < 8; j++) {
        int gr = row0 + r0 + j;
        if (gr < N_EDGES) {
            float se = g_se[gr];
            float ox = fmaf(se, bb.x, acc[j][0]);
            float oy = fmaf(se, bb.y, acc[j][1]);
            float oz = fmaf(se, bb.z, acc[j][2]);
            float ow = fmaf(se, bb.w, acc[j][3]);
            __half2 h0 = __floats2half2_rn(ox, oy);
            __half2 h1 = __floats2half2_rn(oz, ow);
            uint2 r;
            r.x = *reinterpret_cast<const unsigned*>(&h0);
            r.y = *reinterpret_cast<const unsigned*>(&h1);
            ((uint2*)g_Yeh)[(size_t)gr * 32 + tx] = r;
        }
    }
}

// ---------------- 6: node gather-reduce (half2 Ye, 8-unrolled) + relu ----------------
__global__ void node_reduce_kernel(float* __restrict__ out) {
    int gw = (blockIdx.x * blockDim.x + threadIdx.x) >> 5;
    if (gw >= N_NODES) return;
    int lane = threadIdx.x & 31;
    int beg = g_offs_v[gw], end = g_offs_v[gw + 1];
    const uint2* Ye2 = (const uint2*)g_Yeh;
    float sx = 0.f, sy = 0.f, sz = 0.f, sw = 0.f;
    int j = beg;
    for (; j + 8 <= end; j += 8) {
        int ee[8]; uint2 q[8];
        #pragma unroll
        for (int u = 0; u < 8; u++) ee[u] = g_node_adj[j + u];
        #pragma unroll
        for (int u = 0; u < 8; u++) q[u] = Ye2[(size_t)ee[u] * 32 + lane];
        #pragma unroll
        for (int u = 0; u < 8; u++) {
            float2 a = __half22float2(*reinterpret_cast<__half2*>(&q[u].x));
            float2 b = __half22float2(*reinterpret_cast<__half2*>(&q[u].y));
            sx += a.x; sy += a.y; sz += b.x; sw += b.y;
        }
    }
    for (; j < end; j++) {
        int e = g_node_adj[j];
        uint2 q = Ye2[(size_t)e * 32 + lane];
        float2 a = __half22float2(*reinterpret_cast<__half2*>(&q.x));
        float2 b = __half22float2(*reinterpret_cast<__half2*>(&q.y));
        sx += a.x; sy += a.y; sz += b.x; sw += b.y;
    }
    float s = g_inv_sqrt_dv[gw];
    float4 o;
    o.x = fmaxf(sx * s, 0.f);
    o.y = fmaxf(sy * s, 0.f);
    o.z = fmaxf(sz * s, 0.f);
    o.w = fmaxf(sw * s, 0.f);
    ((float4*)out)[(size_t)gw * 32 + lane] = o;
}

// ---------------- launch (forked-stream overlap, graph-capturable) ----------------
extern "C" void kernel_launch(void* const* d_in, const int* in_sizes, int n_in,
                              void* d_out, int out_size) {
    const float* X     = (const float*)d_in[0];
    const float* W     = (const float*)d_in[1];
    const float* bias  = (const float*)d_in[2];
    const int*   v_idx = (const int*)d_in[3];
    const int*   e_idx = (const int*)d_in[4];
    float* out = (float*)d_out;

    (void)in_sizes; (void)n_in; (void)out_size;

    // One-time host resource init (streams/events are not device memory; the
    // captured work is identical on every call). First call is the harness's
    // correctness run (not capturing), so creation happens outside capture.
    static cudaStream_t s_aux = nullptr;
    static cudaEvent_t ev_fork = nullptr, ev_conv = nullptr, ev_scan = nullptr, ev_filln = nullptr;
    if (s_aux == nullptr) {
        cudaStreamCreateWithFlags(&s_aux, cudaStreamNonBlocking);
        cudaEventCreateWithFlags(&ev_fork, cudaEventDisableTiming);
        cudaEventCreateWithFlags(&ev_conv, cudaEventDisableTiming);
        cudaEventCreateWithFlags(&ev_scan, cudaEventDisableTiming);
        cudaEventCreateWithFlags(&ev_filln, cudaEventDisableTiming);
        cudaFuncSetAttribute(gemm_edges_kernel, cudaFuncAttributeMaxDynamicSharedMemorySize,
                             GEMM_SMEM_BYTES);
    }

    // fork: aux stream converts X -> half2 while main does degree+scan
    cudaEventRecord(ev_fork, 0);
    cudaStreamWaitEvent(s_aux, ev_fork, 0);
    convert_kernel<<<(N_NODES * 32 + 255) / 256, 256, 0, s_aux>>>(X);
    cudaEventRecord(ev_conv, s_aux);

    degree_kernel<<<(NNZ + 255) / 256, 256>>>(v_idx, e_idx);
    scan_fused_kernel<<<NB_V + NB_E, 1024>>>();
    cudaEventRecord(ev_scan, 0);

    // aux: node-side fill runs concurrently with edge path
    cudaStreamWaitEvent(s_aux, ev_scan, 0);
    fill_node_kernel<<<(NNZ + 255) / 256, 256, 0, s_aux>>>(v_idx, e_idx);
    cudaEventRecord(ev_filln, s_aux);

    // main: edge path
    fill_edge_kernel<<<(NNZ + 255) / 256, 256>>>(v_idx, e_idx);
    cudaStreamWaitEvent(0, ev_conv, 0);
    edge_reduce_kernel<<<(N_EDGES * 32 + 255) / 256, 256>>>();
    gemm_edges_kernel<<<(N_EDGES + BM - 1) / BM, 256, GEMM_SMEM_BYTES>>>(W, bias);

    // join: node reduce needs node_adj
    cudaStreamWaitEvent(0, ev_filln, 0);
    node_reduce_kernel<<<(N_NODES * 32 + 255) / 256, 256>>>(out);
}